// round 15
// baseline (speedup 1.0000x reference)
#include <cuda_runtime.h>
#include <cuda_fp16.h>
#include <math.h>
#include <stdint.h>

#define BB 2
#define SS 2048
#define DD 1024
#define HH 16
#define HDD 64
#define MM (BB*SS)          // 4096
#define KK DD               // 1024

// ---------------- device scratch (no runtime allocation allowed) ----------------
__device__ __half g_xh[(size_t)MM * KK];           // x fp16 [M,K]
__device__ __half g_w1h[(size_t)KK * 3 * DD];      // W1 fp16, natural [K, 3D]
__device__ __half g_w2h[(size_t)KK * DD];          // W2 fp16, natural [K, D]
__device__ __half g_qh[(size_t)MM * DD];           // Q pre-scaled fp16
__device__ __half g_kh[(size_t)MM * DD];           // K fp16
__device__ __half g_vh[(size_t)MM * DD];           // V fp16
__device__ __half g_ah[(size_t)MM * DD];           // attention out fp16

// ---------------- PTX helpers (base sm_80+ ISA only) ----------
__device__ __forceinline__ uint32_t smem_u32(const void* p) {
    uint32_t a;
    asm("{ .reg .u64 t; cvta.to.shared.u64 t, %1; cvt.u32.u64 %0, t; }" : "=r"(a) : "l"(p));
    return a;
}
__device__ __forceinline__ void cp16(uint32_t dst, const void* src) {
    asm volatile("cp.async.cg.shared.global [%0], [%1], 16;" :: "r"(dst), "l"(src));
}
__device__ __forceinline__ void cp_commit() {
    asm volatile("cp.async.commit_group;" ::: "memory");
}
template <int N>
__device__ __forceinline__ void cp_wait() {
    asm volatile("cp.async.wait_group %0;" :: "n"(N) : "memory");
}
__device__ __forceinline__ void ldsm4(uint32_t* r, uint32_t addr) {
    asm volatile("ldmatrix.sync.aligned.m8n8.x4.shared.b16 {%0,%1,%2,%3}, [%4];"
                 : "=r"(r[0]), "=r"(r[1]), "=r"(r[2]), "=r"(r[3]) : "r"(addr));
}
__device__ __forceinline__ void ldsm4t(uint32_t* r, uint32_t addr) {
    asm volatile("ldmatrix.sync.aligned.m8n8.x4.trans.shared.b16 {%0,%1,%2,%3}, [%4];"
                 : "=r"(r[0]), "=r"(r[1]), "=r"(r[2]), "=r"(r[3]) : "r"(addr));
}
// fp16 inputs, fp32 accumulators
__device__ __forceinline__ void mma2(float* d, const uint32_t* a, uint32_t b0, uint32_t b1) {
    asm volatile(
        "mma.sync.aligned.m16n8k16.row.col.f32.f16.f16.f32 "
        "{%0,%1,%2,%3}, {%4,%5,%6,%7}, {%8,%9}, {%0,%1,%2,%3};"
        : "+f"(d[0]), "+f"(d[1]), "+f"(d[2]), "+f"(d[3])
        : "r"(a[0]), "r"(a[1]), "r"(a[2]), "r"(a[3]), "r"(b0), "r"(b1));
}
// fp16 inputs, fp16 accumulators (throughput probe: 2x if fp32-acc is half-rate)
__device__ __forceinline__ void mma2h(uint32_t* d, const uint32_t* a, uint32_t b0, uint32_t b1) {
    asm volatile(
        "mma.sync.aligned.m16n8k16.row.col.f16.f16.f16.f16 "
        "{%0,%1}, {%2,%3,%4,%5}, {%6,%7}, {%0,%1};"
        : "+r"(d[0]), "+r"(d[1])
        : "r"(a[0]), "r"(a[1]), "r"(a[2]), "r"(a[3]), "r"(b0), "r"(b1));
}
__device__ __forceinline__ uint32_t pkh(float a, float b) {
    __half2 h = __floats2half2_rn(a, b);
    return *(uint32_t*)&h;
}

// 128B-row tile swizzle: chunk c (16B) of row r -> c ^ (r & 7)
__device__ __forceinline__ uint32_t taddr(uint32_t base, int row, int chunk) {
    return base + (uint32_t)(row * 128) + (uint32_t)((chunk ^ (row & 7)) << 4);
}
// 256B-row tile swizzle (B tile, 16 chunks/row)
__device__ __forceinline__ uint32_t taddr256(uint32_t base, int row, int chunk) {
    return base + (uint32_t)(row * 256) + (uint32_t)((chunk ^ (row & 7)) << 4);
}

// ========================== GEMM (pure fp16, BK=64, 2-stage, B natural [K,N]) ==========================
#define TILE_BYTES 16384                // A: 128r x 128B ; B: 64r x 256B
#define STAGE_BYTES (2 * TILE_BYTES)
#define GEMM_SMEM  (2 * STAGE_BYTES)    // 64 KB, 2 stages

// C = Ah[M,K] @ Wh[K,N] + bias   (B fragments via ldmatrix.trans from natural layout)
// MODE 0: fp32 C.  MODE 1: QKV epilogue (Q scaled 1/8 fp16, K fp16, V fp16).
template <int MODE>
__global__ void __launch_bounds__(256, 2) gemm_mma(
    const __half* __restrict__ Ah, const __half* __restrict__ Wh,
    const float* __restrict__ bias, float* __restrict__ C, int N,
    __half* __restrict__ qd, __half* __restrict__ kd, __half* __restrict__ vd)
{
    extern __shared__ char smem[];
    const uint32_t sbase = smem_u32(smem);
    const int tid  = threadIdx.x;
    const int wid  = tid >> 5;
    const int lane = tid & 31;
    const int wm = (wid >> 2) * 64;
    const int wn = (wid & 3) * 32;
    const int m0 = blockIdx.y << 7;
    const int n0 = blockIdx.x << 7;

    const __half* asrc = Ah + (size_t)m0 * KK;
    const __half* bsrc = Wh + n0;

    auto prefetch = [&](int kt, int s) {
        uint32_t stb = sbase + s * STAGE_BYTES;
#pragma unroll
        for (int i = 0; i < 4; i++) {
            int cid = i * 256 + tid;
            int row = cid >> 3, c = cid & 7;
            cp16(stb + taddr(0u, row, c),
                 asrc + (size_t)row * KK + kt * 64 + c * 8);
        }
        uint32_t btb = stb + TILE_BYTES;
#pragma unroll
        for (int i = 0; i < 4; i++) {
            int cid = i * 256 + tid;
            int row = cid >> 4, c = cid & 15;
            cp16(btb + taddr256(0u, row, c),
                 bsrc + (size_t)(kt * 64 + row) * N + c * 8);
        }
    };

    float acc[4][4][4];
#pragma unroll
    for (int i = 0; i < 4; i++)
#pragma unroll
        for (int j = 0; j < 4; j++)
#pragma unroll
            for (int k = 0; k < 4; k++) acc[i][j][k] = 0.f;

    prefetch(0, 0); cp_commit();
    prefetch(1, 1); cp_commit();

    const int KCH = KK / 64;   // 16
    for (int kt = 0; kt < KCH; kt++) {
        const int s = kt & 1;
        if (kt == KCH - 1) cp_wait<0>(); else cp_wait<1>();
        __syncthreads();

        const uint32_t ahb = sbase + s * STAGE_BYTES;
        const uint32_t bhb = ahb + TILE_BYTES;

#pragma unroll
        for (int kh = 0; kh < 4; kh++) {
            const int lrow = lane & 15;
            const int lkc  = kh * 2 + (lane >> 4);

            uint32_t a4[4][4];
#pragma unroll
            for (int mt = 0; mt < 4; mt++)
                ldsm4(a4[mt], taddr(ahb, wm + mt * 16 + lrow, lkc));
#pragma unroll
            for (int nh = 0; nh < 2; nh++) {
                uint32_t rb[4];
                const int ck = (wn >> 3) + nh * 2 + (lane >> 4);
                ldsm4t(rb, taddr256(bhb, kh * 16 + lrow, ck));
                const int nb = nh * 2;
#pragma unroll
                for (int mt = 0; mt < 4; mt++) {
                    mma2(acc[mt][nb],     a4[mt], rb[0], rb[1]);
                    mma2(acc[mt][nb + 1], a4[mt], rb[2], rb[3]);
                }
            }
        }
        __syncthreads();
        if (kt + 2 < KCH) { prefetch(kt + 2, s); cp_commit(); }
    }

    if (MODE == 0) {
#pragma unroll
        for (int mt = 0; mt < 4; mt++) {
#pragma unroll
            for (int nt = 0; nt < 4; nt++) {
                int row = m0 + wm + mt * 16 + (lane >> 2);
                int col = n0 + wn + nt * 8 + ((lane & 3) << 1);
                float b0 = __ldg(bias + col), b1 = __ldg(bias + col + 1);
                float* d = acc[mt][nt];
                *(float2*)(C + (size_t)row * N + col) =
                    make_float2(d[0] + b0, d[1] + b1);
                *(float2*)(C + (size_t)(row + 8) * N + col) =
                    make_float2(d[2] + b0, d[3] + b1);
            }
        }
    } else {
        const int region = n0 >> 10;       // 0=Q, 1=K, 2=V
        const int ncol0  = n0 & 1023;
        const float qs = (region == 0) ? 0.125f : 1.0f;
        __half* dst = (region == 0) ? qd : (region == 1) ? kd : vd;
#pragma unroll
        for (int mt = 0; mt < 4; mt++) {
#pragma unroll
            for (int nt = 0; nt < 4; nt++) {
                int row  = m0 + wm + mt * 16 + (lane >> 2);
                int gcol = n0 + wn + nt * 8 + ((lane & 3) << 1);
                int col  = ncol0 + wn + nt * 8 + ((lane & 3) << 1);
                float b0 = __ldg(bias + gcol), b1 = __ldg(bias + gcol + 1);
                float* d = acc[mt][nt];
                *(uint32_t*)(dst + (size_t)row * DD + col) =
                    pkh((d[0] + b0) * qs, (d[1] + b1) * qs);
                *(uint32_t*)(dst + (size_t)(row + 8) * DD + col) =
                    pkh((d[2] + b0) * qs, (d[3] + b1) * qs);
            }
        }
    }
}

// ========================== fused prep kernel (all elementwise) ==========================
__global__ void __launch_bounds__(256) prep_all(
    const float* __restrict__ x, const float* __restrict__ w1,
    const float* __restrict__ w2,
    __half* __restrict__ xh, __half* __restrict__ w1h, __half* __restrict__ w2h)
{
    const int bid = blockIdx.x;
    const int tid = threadIdx.x;
    const float* in;
    __half* outp;
    int i;
    if (bid < 4096)      { in = x;  outp = xh;  i = bid * 256 + tid; }
    else if (bid < 7168) { in = w1; outp = w1h; i = (bid - 4096) * 256 + tid; }
    else                 { in = w2; outp = w2h; i = (bid - 7168) * 256 + tid; }
    float4 v = ((const float4*)in)[i];
    ((uint2*)outp)[i] = make_uint2(pkh(v.x, v.y), pkh(v.z, v.w));
}

// ========================== tensor-core flash attention (fp16; PV uses fp16 accumulators) ==========================
#define FL_SMEM 49152
// layout: Q 0 (16K), then 2 stages of 16K: {K 8K, V 8K}

__global__ void __launch_bounds__(256, 2) flash_attn_tc(
    const __half* __restrict__ qhg, const __half* __restrict__ khg,
    const __half* __restrict__ vhg, __half* __restrict__ outh)
{
    extern __shared__ char sm[];
    const uint32_t sQ  = smem_u32(sm);
    const uint32_t sKV = sQ + 16384;

    const int tid  = threadIdx.x;
    const int wid  = tid >> 5;
    const int lane = tid & 31;
    const int lrow = lane & 15;
    const int wm   = wid << 4;
    const int qt   = (gridDim.x - 1) - blockIdx.x;   // heavy tiles first
    const int h    = blockIdx.y;
    const int b    = blockIdx.z;
    const int q0   = qt << 7;
    const int kmax = q0 + wm + 15;   // max k-col this warp ever needs (causal)

    // ---- Q + first K/V prefetch (one commit group) ----
    {
        const __half* qsrc = qhg + (size_t)(b * SS + q0) * DD + h * HDD;
#pragma unroll
        for (int i = 0; i < 4; i++) {
            int cid = i * 256 + tid;
            int row = cid >> 3, c = cid & 7;
            cp16(sQ + taddr(0u, row, c), qsrc + (size_t)row * DD + c * 8);
        }
    }

    auto pf = [&](int kt, int st) {
        uint32_t sb = sKV + st * 16384;
        const size_t goff = (size_t)(b * SS + (kt << 6)) * DD + h * HDD;
#pragma unroll
        for (int t = 0; t < 4; t++) {
            const __half* gp = (t < 2) ? khg : vhg;
            int cid = ((t & 1) << 8) + tid;
            int row = cid >> 3, c = cid & 7;
            cp16(sb + (uint32_t)((t >> 1) << 13) + taddr(0u, row, c),
                 gp + goff + (size_t)row * DD + c * 8);
        }
    };

    pf(0, 0); cp_commit();

    float o[8][4];
#pragma unroll
    for (int nt = 0; nt < 8; nt++)
#pragma unroll
        for (int k = 0; k < 4; k++) o[nt][k] = 0.f;
    float m0r = -INFINITY, m1r = -INFINITY, l0r = 0.f, l1r = 0.f;

    const int grow0 = q0 + wm + (lane >> 2);
    const int grow1 = grow0 + 8;
    const int nkt = 2 * qt + 2;

    for (int kt = 0; kt < nkt; kt++) {
        const int k0 = kt << 6;
        const int st = kt & 1;
        if (kt + 1 < nkt) {
            pf(kt + 1, st ^ 1); cp_commit();
            cp_wait<1>();
        } else {
            cp_wait<0>();
        }
        __syncthreads();

        const uint32_t sKb = sKV + st * 16384;
        const uint32_t sVb = sKb + 8192;

        // ---- S = Q K^T (fp32 acc; warp-uniform skip of fully-masked halves) ----
        float s[8][4];
#pragma unroll
        for (int nt = 0; nt < 8; nt++)
#pragma unroll
            for (int k = 0; k < 4; k++) s[nt][k] = 0.f;

#pragma unroll
        for (int ks = 0; ks < 4; ks++) {
            const int ck = ks * 2 + (lane >> 4);
            uint32_t q4[4];
            ldsm4(q4, taddr(sQ, wm + lrow, ck));
#pragma unroll
            for (int half = 0; half < 2; half++) {
                if (k0 + half * 32 > kmax) continue;   // S stays exactly 0
                uint32_t r0[4], r1[4];
                ldsm4(r0, taddr(sKb, half * 32 + lrow, ck));
                ldsm4(r1, taddr(sKb, half * 32 + 16 + lrow, ck));
                const int n0 = half * 4;
                mma2(s[n0],     q4, r0[0], r0[2]);
                mma2(s[n0 + 1], q4, r0[1], r0[3]);
                mma2(s[n0 + 2], q4, r1[0], r1[2]);
                mma2(s[n0 + 3], q4, r1[1], r1[3]);
            }
        }

        // ---- causal mask ----
        if (k0 + 63 > grow0) {
#pragma unroll
            for (int nt = 0; nt < 8; nt++) {
                int col = k0 + nt * 8 + ((lane & 3) << 1);
                if (col > grow0)     s[nt][0] = -1e30f;
                if (col + 1 > grow0) s[nt][1] = -1e30f;
                if (col > grow1)     s[nt][2] = -1e30f;
                if (col + 1 > grow1) s[nt][3] = -1e30f;
            }
        }

        // ---- online softmax ----
        float ml0 = -INFINITY, ml1 = -INFINITY;
#pragma unroll
        for (int nt = 0; nt < 8; nt++) {
            ml0 = fmaxf(ml0, fmaxf(s[nt][0], s[nt][1]));
            ml1 = fmaxf(ml1, fmaxf(s[nt][2], s[nt][3]));
        }
        ml0 = fmaxf(ml0, __shfl_xor_sync(0xffffffffu, ml0, 1));
        ml0 = fmaxf(ml0, __shfl_xor_sync(0xffffffffu, ml0, 2));
        ml1 = fmaxf(ml1, __shfl_xor_sync(0xffffffffu, ml1, 1));
        ml1 = fmaxf(ml1, __shfl_xor_sync(0xffffffffu, ml1, 2));
        float mn0 = fmaxf(m0r, ml0), mn1 = fmaxf(m1r, ml1);
        float c0 = __expf(m0r - mn0), c1 = __expf(m1r - mn1);
        m0r = mn0; m1r = mn1;
        float rs0 = 0.f, rs1 = 0.f;
#pragma unroll
        for (int nt = 0; nt < 8; nt++) {
            s[nt][0] = __expf(s[nt][0] - mn0);
            s[nt][1] = __expf(s[nt][1] - mn0);
            s[nt][2] = __expf(s[nt][2] - mn1);
            s[nt][3] = __expf(s[nt][3] - mn1);
            rs0 += s[nt][0] + s[nt][1];
            rs1 += s[nt][2] + s[nt][3];
        }
        rs0 += __shfl_xor_sync(0xffffffffu, rs0, 1);
        rs0 += __shfl_xor_sync(0xffffffffu, rs0, 2);
        rs1 += __shfl_xor_sync(0xffffffffu, rs1, 1);
        rs1 += __shfl_xor_sync(0xffffffffu, rs1, 2);
        l0r = l0r * c0 + rs0;
        l1r = l1r * c1 + rs1;
        // skip exact-noop rescale (c == 1.0 when max unchanged)
        if (!__all_sync(0xffffffffu, (c0 == 1.f) && (c1 == 1.f))) {
#pragma unroll
            for (int nt = 0; nt < 8; nt++) {
                o[nt][0] *= c0; o[nt][1] *= c0;
                o[nt][2] *= c1; o[nt][3] *= c1;
            }
        }

        // ---- O_tile = P V with fp16 accumulators (K=64 per tile), then promote ----
        uint32_t oh[8][2];
#pragma unroll
        for (int nt = 0; nt < 8; nt++) { oh[nt][0] = 0u; oh[nt][1] = 0u; }

#pragma unroll
        for (int j = 0; j < 4; j++) {
            if (k0 + j * 16 > kmax) continue;   // P fragment all exact zeros
            uint32_t aP[4];
            aP[0] = pkh(s[2 * j][0],     s[2 * j][1]);
            aP[1] = pkh(s[2 * j][2],     s[2 * j][3]);
            aP[2] = pkh(s[2 * j + 1][0], s[2 * j + 1][1]);
            aP[3] = pkh(s[2 * j + 1][2], s[2 * j + 1][3]);
#pragma unroll
            for (int half = 0; half < 2; half++) {
                const int ck0 = half * 4 + (lane >> 4);
                const int ck1 = ck0 + 2;
                uint32_t v0[4], v1[4];
                ldsm4t(v0, taddr(sVb, j * 16 + lrow, ck0));
                ldsm4t(v1, taddr(sVb, j * 16 + lrow, ck1));
                const int c0i = half * 4;
                mma2h(oh[c0i],     aP, v0[0], v0[1]);
                mma2h(oh[c0i + 1], aP, v0[2], v0[3]);
                mma2h(oh[c0i + 2], aP, v1[0], v1[1]);
                mma2h(oh[c0i + 3], aP, v1[2], v1[3]);
            }
        }
        // promote fp16 tile-partials into fp32 running O
#pragma unroll
        for (int nt = 0; nt < 8; nt++) {
            float2 f0 = __half22float2(*(__half2*)&oh[nt][0]);
            float2 f1 = __half22float2(*(__half2*)&oh[nt][1]);
            o[nt][0] += f0.x; o[nt][1] += f0.y;
            o[nt][2] += f1.x; o[nt][3] += f1.y;
        }
        __syncthreads();
    }

    // ---- epilogue: normalize, store fp16 merged-head [B*S, D] ----
    float inv0 = 1.f / l0r, inv1 = 1.f / l1r;
    size_t r0 = (size_t)(b * SS + grow0) * DD;
    size_t r1 = (size_t)(b * SS + grow1) * DD;
    int colb = h * HDD + ((lane & 3) << 1);
#pragma unroll
    for (int nt = 0; nt < 8; nt++) {
        int col = colb + nt * 8;
        *(uint32_t*)(outh + r0 + col) = pkh(o[nt][0] * inv0, o[nt][1] * inv0);
        *(uint32_t*)(outh + r1 + col) = pkh(o[nt][2] * inv1, o[nt][3] * inv1);
    }
}

// ---------------------------------------------------------------------------
extern "C" void kernel_launch(void* const* d_in, const int* in_sizes, int n_in,
                              void* d_out, int out_size)
{
    const float* x  = (const float*)d_in[0];
    const float* w1 = (const float*)d_in[1];
    const float* b1 = (const float*)d_in[2];
    const float* w2 = (const float*)d_in[3];
    const float* b2 = (const float*)d_in[4];
    float* out = (float*)d_out;

    __half *xh, *w1h, *w2h, *qh, *kh, *vh, *ah;
    cudaGetSymbolAddress((void**)&xh,  g_xh);
    cudaGetSymbolAddress((void**)&w1h, g_w1h);
    cudaGetSymbolAddress((void**)&w2h, g_w2h);
    cudaGetSymbolAddress((void**)&qh,  g_qh);
    cudaGetSymbolAddress((void**)&kh,  g_kh);
    cudaGetSymbolAddress((void**)&vh,  g_vh);
    cudaGetSymbolAddress((void**)&ah,  g_ah);

    static int inited = 0;
    if (!inited) {
        cudaFuncSetAttribute(gemm_mma<0>,
            cudaFuncAttributeMaxDynamicSharedMemorySize, GEMM_SMEM);
        cudaFuncSetAttribute(gemm_mma<1>,
            cudaFuncAttributeMaxDynamicSharedMemorySize, GEMM_SMEM);
        cudaFuncSetAttribute(flash_attn_tc,
            cudaFuncAttributeMaxDynamicSharedMemorySize, FL_SMEM);
        inited = 1;
    }

    // 0) fused operand prep (pure elementwise converts; weights stay [K,N])
    prep_all<<<8192, 256>>>(x, w1, w2, xh, w1h, w2h);

    // 1) QKV projection with fused Q-scale + fp16 epilogue
    gemm_mma<1><<<dim3(3 * DD / 128, MM / 128), 256, GEMM_SMEM>>>(
        xh, w1h, b1, nullptr, 3 * DD, qh, kh, vh);

    // 2) causal flash attention (QK fp32-acc, PV fp16-acc probe)
    flash_attn_tc<<<dim3(SS / 128, HH, BB), 256, FL_SMEM>>>(qh, kh, vh, ah);

    // 3) output projection (fp32 out + bias)
    gemm_mma<0><<<dim3(DD / 128, MM / 128), 256, GEMM_SMEM>>>(
        ah, w2h, b2, out, DD, nullptr, nullptr, nullptr);
}

// round 16
// speedup vs baseline: 1.0292x; 1.0292x over previous
#include <cuda_runtime.h>
#include <cuda_fp16.h>
#include <math.h>
#include <stdint.h>

#define BB 2
#define SS 2048
#define DD 1024
#define HH 16
#define HDD 64
#define MM (BB*SS)          // 4096
#define KK DD               // 1024

// ---------------- device scratch (no runtime allocation allowed) ----------------
__device__ __half g_xh[(size_t)MM * KK];           // x fp16 [M,K]
__device__ __half g_w1h[(size_t)KK * 3 * DD];      // W1 fp16, natural [K, 3D]
__device__ __half g_w2h[(size_t)KK * DD];          // W2 fp16, natural [K, D]
__device__ __half g_qh[(size_t)MM * DD];           // Q pre-scaled fp16
__device__ __half g_kh[(size_t)MM * DD];           // K fp16
__device__ __half g_vh[(size_t)MM * DD];           // V fp16
__device__ __half g_ah[(size_t)MM * DD];           // attention out fp16

// ---------------- PTX helpers (base sm_80+ ISA only) ----------
__device__ __forceinline__ uint32_t smem_u32(const void* p) {
    uint32_t a;
    asm("{ .reg .u64 t; cvta.to.shared.u64 t, %1; cvt.u32.u64 %0, t; }" : "=r"(a) : "l"(p));
    return a;
}
__device__ __forceinline__ void cp16(uint32_t dst, const void* src) {
    asm volatile("cp.async.cg.shared.global [%0], [%1], 16;" :: "r"(dst), "l"(src));
}
__device__ __forceinline__ void cp_commit() {
    asm volatile("cp.async.commit_group;" ::: "memory");
}
template <int N>
__device__ __forceinline__ void cp_wait() {
    asm volatile("cp.async.wait_group %0;" :: "n"(N) : "memory");
}
__device__ __forceinline__ void ldsm4(uint32_t* r, uint32_t addr) {
    asm volatile("ldmatrix.sync.aligned.m8n8.x4.shared.b16 {%0,%1,%2,%3}, [%4];"
                 : "=r"(r[0]), "=r"(r[1]), "=r"(r[2]), "=r"(r[3]) : "r"(addr));
}
__device__ __forceinline__ void ldsm4t(uint32_t* r, uint32_t addr) {
    asm volatile("ldmatrix.sync.aligned.m8n8.x4.trans.shared.b16 {%0,%1,%2,%3}, [%4];"
                 : "=r"(r[0]), "=r"(r[1]), "=r"(r[2]), "=r"(r[3]) : "r"(addr));
}
__device__ __forceinline__ void mma2(float* d, const uint32_t* a, uint32_t b0, uint32_t b1) {
    asm volatile(
        "mma.sync.aligned.m16n8k16.row.col.f32.f16.f16.f32 "
        "{%0,%1,%2,%3}, {%4,%5,%6,%7}, {%8,%9}, {%0,%1,%2,%3};"
        : "+f"(d[0]), "+f"(d[1]), "+f"(d[2]), "+f"(d[3])
        : "r"(a[0]), "r"(a[1]), "r"(a[2]), "r"(a[3]), "r"(b0), "r"(b1));
}
__device__ __forceinline__ uint32_t pkh(float a, float b) {
    __half2 h = __floats2half2_rn(a, b);
    return *(uint32_t*)&h;
}

// 128B-row tile swizzle: chunk c (16B) of row r -> c ^ (r & 7)
__device__ __forceinline__ uint32_t taddr(uint32_t base, int row, int chunk) {
    return base + (uint32_t)(row * 128) + (uint32_t)((chunk ^ (row & 7)) << 4);
}
// 256B-row tile swizzle (B tile, 16 chunks/row)
__device__ __forceinline__ uint32_t taddr256(uint32_t base, int row, int chunk) {
    return base + (uint32_t)(row * 256) + (uint32_t)((chunk ^ (row & 7)) << 4);
}

// ========================== GEMM (pure fp16, BK=64, 2-stage, B natural [K,N]) ==========================
#define TILE_BYTES 16384                // A: 128r x 128B ; B: 64r x 256B
#define STAGE_BYTES (2 * TILE_BYTES)
#define GEMM_SMEM  (2 * STAGE_BYTES)    // 64 KB, 2 stages

// C = Ah[M,K] @ Wh[K,N] + bias   (B fragments via ldmatrix.trans from natural layout)
// MODE 0: fp32 C.  MODE 1: QKV epilogue (Q scaled 1/8 fp16, K fp16, V fp16).
template <int MODE>
__global__ void __launch_bounds__(256, 2) gemm_mma(
    const __half* __restrict__ Ah, const __half* __restrict__ Wh,
    const float* __restrict__ bias, float* __restrict__ C, int N,
    __half* __restrict__ qd, __half* __restrict__ kd, __half* __restrict__ vd)
{
    extern __shared__ char smem[];
    const uint32_t sbase = smem_u32(smem);
    const int tid  = threadIdx.x;
    const int wid  = tid >> 5;
    const int lane = tid & 31;
    const int wm = (wid >> 2) * 64;
    const int wn = (wid & 3) * 32;
    const int m0 = blockIdx.y << 7;
    const int n0 = blockIdx.x << 7;

    const __half* asrc = Ah + (size_t)m0 * KK;
    const __half* bsrc = Wh + n0;

    auto prefetch = [&](int kt, int s) {
        uint32_t stb = sbase + s * STAGE_BYTES;
#pragma unroll
        for (int i = 0; i < 4; i++) {
            int cid = i * 256 + tid;
            int row = cid >> 3, c = cid & 7;
            cp16(stb + taddr(0u, row, c),
                 asrc + (size_t)row * KK + kt * 64 + c * 8);
        }
        uint32_t btb = stb + TILE_BYTES;
#pragma unroll
        for (int i = 0; i < 4; i++) {
            int cid = i * 256 + tid;
            int row = cid >> 4, c = cid & 15;
            cp16(btb + taddr256(0u, row, c),
                 bsrc + (size_t)(kt * 64 + row) * N + c * 8);
        }
    };

    float acc[4][4][4];
#pragma unroll
    for (int i = 0; i < 4; i++)
#pragma unroll
        for (int j = 0; j < 4; j++)
#pragma unroll
            for (int k = 0; k < 4; k++) acc[i][j][k] = 0.f;

    prefetch(0, 0); cp_commit();
    prefetch(1, 1); cp_commit();

    const int KCH = KK / 64;   // 16
    for (int kt = 0; kt < KCH; kt++) {
        const int s = kt & 1;
        if (kt == KCH - 1) cp_wait<0>(); else cp_wait<1>();
        __syncthreads();

        const uint32_t ahb = sbase + s * STAGE_BYTES;
        const uint32_t bhb = ahb + TILE_BYTES;

#pragma unroll
        for (int kh = 0; kh < 4; kh++) {
            const int lrow = lane & 15;
            const int lkc  = kh * 2 + (lane >> 4);

            uint32_t a4[4][4];
#pragma unroll
            for (int mt = 0; mt < 4; mt++)
                ldsm4(a4[mt], taddr(ahb, wm + mt * 16 + lrow, lkc));
#pragma unroll
            for (int nh = 0; nh < 2; nh++) {
                uint32_t rb[4];
                const int ck = (wn >> 3) + nh * 2 + (lane >> 4);
                ldsm4t(rb, taddr256(bhb, kh * 16 + lrow, ck));
                const int nb = nh * 2;
#pragma unroll
                for (int mt = 0; mt < 4; mt++) {
                    mma2(acc[mt][nb],     a4[mt], rb[0], rb[1]);
                    mma2(acc[mt][nb + 1], a4[mt], rb[2], rb[3]);
                }
            }
        }
        __syncthreads();
        if (kt + 2 < KCH) { prefetch(kt + 2, s); cp_commit(); }
    }

    if (MODE == 0) {
#pragma unroll
        for (int mt = 0; mt < 4; mt++) {
#pragma unroll
            for (int nt = 0; nt < 4; nt++) {
                int row = m0 + wm + mt * 16 + (lane >> 2);
                int col = n0 + wn + nt * 8 + ((lane & 3) << 1);
                float b0 = __ldg(bias + col), b1 = __ldg(bias + col + 1);
                float* d = acc[mt][nt];
                *(float2*)(C + (size_t)row * N + col) =
                    make_float2(d[0] + b0, d[1] + b1);
                *(float2*)(C + (size_t)(row + 8) * N + col) =
                    make_float2(d[2] + b0, d[3] + b1);
            }
        }
    } else {
        const int region = n0 >> 10;       // 0=Q, 1=K, 2=V
        const int ncol0  = n0 & 1023;
        const float qs = (region == 0) ? 0.125f : 1.0f;
        __half* dst = (region == 0) ? qd : (region == 1) ? kd : vd;
#pragma unroll
        for (int mt = 0; mt < 4; mt++) {
#pragma unroll
            for (int nt = 0; nt < 4; nt++) {
                int row  = m0 + wm + mt * 16 + (lane >> 2);
                int gcol = n0 + wn + nt * 8 + ((lane & 3) << 1);
                int col  = ncol0 + wn + nt * 8 + ((lane & 3) << 1);
                float b0 = __ldg(bias + gcol), b1 = __ldg(bias + gcol + 1);
                float* d = acc[mt][nt];
                *(uint32_t*)(dst + (size_t)row * DD + col) =
                    pkh((d[0] + b0) * qs, (d[1] + b1) * qs);
                *(uint32_t*)(dst + (size_t)(row + 8) * DD + col) =
                    pkh((d[2] + b0) * qs, (d[3] + b1) * qs);
            }
        }
    }
}

// ========================== fused prep kernel (all elementwise) ==========================
__global__ void __launch_bounds__(256) prep_all(
    const float* __restrict__ x, const float* __restrict__ w1,
    const float* __restrict__ w2,
    __half* __restrict__ xh, __half* __restrict__ w1h, __half* __restrict__ w2h)
{
    const int bid = blockIdx.x;
    const int tid = threadIdx.x;
    const float* in;
    __half* outp;
    int i;
    if (bid < 4096)      { in = x;  outp = xh;  i = bid * 256 + tid; }
    else if (bid < 7168) { in = w1; outp = w1h; i = (bid - 4096) * 256 + tid; }
    else                 { in = w2; outp = w2h; i = (bid - 7168) * 256 + tid; }
    float4 v = ((const float4*)in)[i];
    ((uint2*)outp)[i] = make_uint2(pkh(v.x, v.y), pkh(v.z, v.w));
}

// ========================== tensor-core flash attention (pure fp16) ==========================
#define FL_SMEM 49152
// layout: Q 0 (16K), then 2 stages of 16K: {K 8K, V 8K}

__global__ void __launch_bounds__(256, 2) flash_attn_tc(
    const __half* __restrict__ qhg, const __half* __restrict__ khg,
    const __half* __restrict__ vhg, __half* __restrict__ outh)
{
    extern __shared__ char sm[];
    const uint32_t sQ  = smem_u32(sm);
    const uint32_t sKV = sQ + 16384;

    const int tid  = threadIdx.x;
    const int wid  = tid >> 5;
    const int lane = tid & 31;
    const int lrow = lane & 15;
    const int wm   = wid << 4;
    const int qt   = (gridDim.x - 1) - blockIdx.x;   // heavy tiles first
    const int h    = blockIdx.y;
    const int b    = blockIdx.z;
    const int q0   = qt << 7;
    const int kmax = q0 + wm + 15;   // max k-col this warp ever needs (causal)

    // ---- Q + first K/V prefetch (one commit group) ----
    {
        const __half* qsrc = qhg + (size_t)(b * SS + q0) * DD + h * HDD;
#pragma unroll
        for (int i = 0; i < 4; i++) {
            int cid = i * 256 + tid;
            int row = cid >> 3, c = cid & 7;
            cp16(sQ + taddr(0u, row, c), qsrc + (size_t)row * DD + c * 8);
        }
    }

    auto pf = [&](int kt, int st) {
        uint32_t sb = sKV + st * 16384;
        const size_t goff = (size_t)(b * SS + (kt << 6)) * DD + h * HDD;
#pragma unroll
        for (int t = 0; t < 4; t++) {
            const __half* gp = (t < 2) ? khg : vhg;
            int cid = ((t & 1) << 8) + tid;
            int row = cid >> 3, c = cid & 7;
            cp16(sb + (uint32_t)((t >> 1) << 13) + taddr(0u, row, c),
                 gp + goff + (size_t)row * DD + c * 8);
        }
    };

    pf(0, 0); cp_commit();

    float o[8][4];
#pragma unroll
    for (int nt = 0; nt < 8; nt++)
#pragma unroll
        for (int k = 0; k < 4; k++) o[nt][k] = 0.f;
    float m0r = -INFINITY, m1r = -INFINITY, l0r = 0.f, l1r = 0.f;

    const int grow0 = q0 + wm + (lane >> 2);
    const int grow1 = grow0 + 8;
    const int nkt = 2 * qt + 2;

    for (int kt = 0; kt < nkt; kt++) {
        const int k0 = kt << 6;
        const int st = kt & 1;
        if (kt + 1 < nkt) {
            pf(kt + 1, st ^ 1); cp_commit();
            cp_wait<1>();
        } else {
            cp_wait<0>();
        }
        __syncthreads();

        const uint32_t sKb = sKV + st * 16384;
        const uint32_t sVb = sKb + 8192;

        // ---- S = Q K^T (warp-uniform skip of fully-masked halves) ----
        float s[8][4];
#pragma unroll
        for (int nt = 0; nt < 8; nt++)
#pragma unroll
            for (int k = 0; k < 4; k++) s[nt][k] = 0.f;

#pragma unroll
        for (int ks = 0; ks < 4; ks++) {
            const int ck = ks * 2 + (lane >> 4);
            uint32_t q4[4];
            ldsm4(q4, taddr(sQ, wm + lrow, ck));
#pragma unroll
            for (int half = 0; half < 2; half++) {
                if (k0 + half * 32 > kmax) continue;   // S stays exactly 0
                uint32_t r0[4], r1[4];
                ldsm4(r0, taddr(sKb, half * 32 + lrow, ck));
                ldsm4(r1, taddr(sKb, half * 32 + 16 + lrow, ck));
                const int n0 = half * 4;
                mma2(s[n0],     q4, r0[0], r0[2]);
                mma2(s[n0 + 1], q4, r0[1], r0[3]);
                mma2(s[n0 + 2], q4, r1[0], r1[2]);
                mma2(s[n0 + 3], q4, r1[1], r1[3]);
            }
        }

        // ---- causal mask ----
        if (k0 + 63 > grow0) {
#pragma unroll
            for (int nt = 0; nt < 8; nt++) {
                int col = k0 + nt * 8 + ((lane & 3) << 1);
                if (col > grow0)     s[nt][0] = -1e30f;
                if (col + 1 > grow0) s[nt][1] = -1e30f;
                if (col > grow1)     s[nt][2] = -1e30f;
                if (col + 1 > grow1) s[nt][3] = -1e30f;
            }
        }

        // ---- online softmax ----
        float ml0 = -INFINITY, ml1 = -INFINITY;
#pragma unroll
        for (int nt = 0; nt < 8; nt++) {
            ml0 = fmaxf(ml0, fmaxf(s[nt][0], s[nt][1]));
            ml1 = fmaxf(ml1, fmaxf(s[nt][2], s[nt][3]));
        }
        ml0 = fmaxf(ml0, __shfl_xor_sync(0xffffffffu, ml0, 1));
        ml0 = fmaxf(ml0, __shfl_xor_sync(0xffffffffu, ml0, 2));
        ml1 = fmaxf(ml1, __shfl_xor_sync(0xffffffffu, ml1, 1));
        ml1 = fmaxf(ml1, __shfl_xor_sync(0xffffffffu, ml1, 2));
        float mn0 = fmaxf(m0r, ml0), mn1 = fmaxf(m1r, ml1);
        float c0 = __expf(m0r - mn0), c1 = __expf(m1r - mn1);
        m0r = mn0; m1r = mn1;
        float rs0 = 0.f, rs1 = 0.f;
#pragma unroll
        for (int nt = 0; nt < 8; nt++) {
            s[nt][0] = __expf(s[nt][0] - mn0);
            s[nt][1] = __expf(s[nt][1] - mn0);
            s[nt][2] = __expf(s[nt][2] - mn1);
            s[nt][3] = __expf(s[nt][3] - mn1);
            rs0 += s[nt][0] + s[nt][1];
            rs1 += s[nt][2] + s[nt][3];
        }
        rs0 += __shfl_xor_sync(0xffffffffu, rs0, 1);
        rs0 += __shfl_xor_sync(0xffffffffu, rs0, 2);
        rs1 += __shfl_xor_sync(0xffffffffu, rs1, 1);
        rs1 += __shfl_xor_sync(0xffffffffu, rs1, 2);
        l0r = l0r * c0 + rs0;
        l1r = l1r * c1 + rs1;
        // skip exact-noop rescale (c == 1.0 when max unchanged)
        if (!__all_sync(0xffffffffu, (c0 == 1.f) && (c1 == 1.f))) {
#pragma unroll
            for (int nt = 0; nt < 8; nt++) {
                o[nt][0] *= c0; o[nt][1] *= c0;
                o[nt][2] *= c1; o[nt][3] *= c1;
            }
        }

        // ---- O += P V (skip j-slices whose P block is exactly zero) ----
#pragma unroll
        for (int j = 0; j < 4; j++) {
            if (k0 + j * 16 > kmax) continue;   // P fragment all exact zeros
            uint32_t aP[4];
            aP[0] = pkh(s[2 * j][0],     s[2 * j][1]);
            aP[1] = pkh(s[2 * j][2],     s[2 * j][3]);
            aP[2] = pkh(s[2 * j + 1][0], s[2 * j + 1][1]);
            aP[3] = pkh(s[2 * j + 1][2], s[2 * j + 1][3]);
#pragma unroll
            for (int half = 0; half < 2; half++) {
                const int ck0 = half * 4 + (lane >> 4);
                const int ck1 = ck0 + 2;
                uint32_t v0[4], v1[4];
                ldsm4t(v0, taddr(sVb, j * 16 + lrow, ck0));
                ldsm4t(v1, taddr(sVb, j * 16 + lrow, ck1));
                const int c0i = half * 4;
                mma2(o[c0i],     aP, v0[0], v0[1]);
                mma2(o[c0i + 1], aP, v0[2], v0[3]);
                mma2(o[c0i + 2], aP, v1[0], v1[1]);
                mma2(o[c0i + 3], aP, v1[2], v1[3]);
            }
        }
        __syncthreads();
    }

    // ---- epilogue: normalize, store fp16 merged-head [B*S, D] ----
    float inv0 = 1.f / l0r, inv1 = 1.f / l1r;
    size_t r0 = (size_t)(b * SS + grow0) * DD;
    size_t r1 = (size_t)(b * SS + grow1) * DD;
    int colb = h * HDD + ((lane & 3) << 1);
#pragma unroll
    for (int nt = 0; nt < 8; nt++) {
        int col = colb + nt * 8;
        *(uint32_t*)(outh + r0 + col) = pkh(o[nt][0] * inv0, o[nt][1] * inv0);
        *(uint32_t*)(outh + r1 + col) = pkh(o[nt][2] * inv1, o[nt][3] * inv1);
    }
}

// ---------------------------------------------------------------------------
extern "C" void kernel_launch(void* const* d_in, const int* in_sizes, int n_in,
                              void* d_out, int out_size)
{
    const float* x  = (const float*)d_in[0];
    const float* w1 = (const float*)d_in[1];
    const float* b1 = (const float*)d_in[2];
    const float* w2 = (const float*)d_in[3];
    const float* b2 = (const float*)d_in[4];
    float* out = (float*)d_out;

    __half *xh, *w1h, *w2h, *qh, *kh, *vh, *ah;
    cudaGetSymbolAddress((void**)&xh,  g_xh);
    cudaGetSymbolAddress((void**)&w1h, g_w1h);
    cudaGetSymbolAddress((void**)&w2h, g_w2h);
    cudaGetSymbolAddress((void**)&qh,  g_qh);
    cudaGetSymbolAddress((void**)&kh,  g_kh);
    cudaGetSymbolAddress((void**)&vh,  g_vh);
    cudaGetSymbolAddress((void**)&ah,  g_ah);

    static int inited = 0;
    if (!inited) {
        cudaFuncSetAttribute(gemm_mma<0>,
            cudaFuncAttributeMaxDynamicSharedMemorySize, GEMM_SMEM);
        cudaFuncSetAttribute(gemm_mma<1>,
            cudaFuncAttributeMaxDynamicSharedMemorySize, GEMM_SMEM);
        cudaFuncSetAttribute(flash_attn_tc,
            cudaFuncAttributeMaxDynamicSharedMemorySize, FL_SMEM);
        inited = 1;
    }

    // 0) fused operand prep (pure elementwise converts; weights stay [K,N])
    prep_all<<<8192, 256>>>(x, w1, w2, xh, w1h, w2h);

    // 1) QKV projection with fused Q-scale + fp16 epilogue
    gemm_mma<1><<<dim3(3 * DD / 128, MM / 128), 256, GEMM_SMEM>>>(
        xh, w1h, b1, nullptr, 3 * DD, qh, kh, vh);

    // 2) causal flash attention on tensor cores (128-row q-tiles, 2 CTA/SM)
    flash_attn_tc<<<dim3(SS / 128, HH, BB), 256, FL_SMEM>>>(qh, kh, vh, ah);

    // 3) output projection (fp32 out + bias)
    gemm_mma<0><<<dim3(DD / 128, MM / 128), 256, GEMM_SMEM>>>(
        ah, w2h, b2, out, DD, nullptr, nullptr, nullptr);
}

// round 17
// speedup vs baseline: 1.1405x; 1.1081x over previous
#include <cuda_runtime.h>
#include <cuda_fp16.h>
#include <math.h>
#include <stdint.h>

#define BB 2
#define SS 2048
#define DD 1024
#define HH 16
#define HDD 64
#define MM (BB*SS)          // 4096
#define KK DD               // 1024

// ---------------- device scratch (no runtime allocation allowed) ----------------
__device__ __half g_xh[(size_t)MM * KK];           // x fp16 [M,K]
__device__ __half g_w1h[(size_t)KK * 3 * DD];      // W1 fp16, natural [K, 3D]
__device__ __half g_w2h[(size_t)KK * DD];          // W2 fp16, natural [K, D]
__device__ __half g_qh[(size_t)MM * DD];           // Q pre-scaled fp16
__device__ __half g_kh[(size_t)MM * DD];           // K fp16
__device__ __half g_vh[(size_t)MM * DD];           // V fp16
__device__ __half g_ah[(size_t)MM * DD];           // attention out fp16

// ---------------- PTX helpers (base sm_80+ ISA only) ----------
__device__ __forceinline__ uint32_t smem_u32(const void* p) {
    uint32_t a;
    asm("{ .reg .u64 t; cvta.to.shared.u64 t, %1; cvt.u32.u64 %0, t; }" : "=r"(a) : "l"(p));
    return a;
}
__device__ __forceinline__ void cp16(uint32_t dst, const void* src) {
    asm volatile("cp.async.cg.shared.global [%0], [%1], 16;" :: "r"(dst), "l"(src));
}
__device__ __forceinline__ void cp_commit() {
    asm volatile("cp.async.commit_group;" ::: "memory");
}
template <int N>
__device__ __forceinline__ void cp_wait() {
    asm volatile("cp.async.wait_group %0;" :: "n"(N) : "memory");
}
__device__ __forceinline__ void ldsm4(uint32_t* r, uint32_t addr) {
    asm volatile("ldmatrix.sync.aligned.m8n8.x4.shared.b16 {%0,%1,%2,%3}, [%4];"
                 : "=r"(r[0]), "=r"(r[1]), "=r"(r[2]), "=r"(r[3]) : "r"(addr));
}
__device__ __forceinline__ void ldsm4t(uint32_t* r, uint32_t addr) {
    asm volatile("ldmatrix.sync.aligned.m8n8.x4.trans.shared.b16 {%0,%1,%2,%3}, [%4];"
                 : "=r"(r[0]), "=r"(r[1]), "=r"(r[2]), "=r"(r[3]) : "r"(addr));
}
__device__ __forceinline__ void mma2(float* d, const uint32_t* a, uint32_t b0, uint32_t b1) {
    asm volatile(
        "mma.sync.aligned.m16n8k16.row.col.f32.f16.f16.f32 "
        "{%0,%1,%2,%3}, {%4,%5,%6,%7}, {%8,%9}, {%0,%1,%2,%3};"
        : "+f"(d[0]), "+f"(d[1]), "+f"(d[2]), "+f"(d[3])
        : "r"(a[0]), "r"(a[1]), "r"(a[2]), "r"(a[3]), "r"(b0), "r"(b1));
}
__device__ __forceinline__ uint32_t pkh(float a, float b) {
    __half2 h = __floats2half2_rn(a, b);
    return *(uint32_t*)&h;
}

// 128B-row tile swizzle: chunk c (16B) of row r -> c ^ (r & 7)
__device__ __forceinline__ uint32_t taddr(uint32_t base, int row, int chunk) {
    return base + (uint32_t)(row * 128) + (uint32_t)((chunk ^ (row & 7)) << 4);
}
// 256B-row tile swizzle (B tile, 16 chunks/row)
__device__ __forceinline__ uint32_t taddr256(uint32_t base, int row, int chunk) {
    return base + (uint32_t)(row * 256) + (uint32_t)((chunk ^ (row & 7)) << 4);
}

// ========================== GEMM (pure fp16, BK=64, 2-stage, B natural [K,N]) ==========================
#define TILE_BYTES 16384                // A: 128r x 128B ; B: 64r x 256B
#define STAGE_BYTES (2 * TILE_BYTES)
#define GEMM_SMEM  (2 * STAGE_BYTES)    // 64 KB, 2 stages

// C = Ah[M,K] @ Wh[K,N] + bias   (B fragments via ldmatrix.trans from natural layout)
// MODE 0: fp32 C.  MODE 1: QKV epilogue (Q scaled 1/8 fp16, K fp16, V fp16).
template <int MODE>
__global__ void __launch_bounds__(256, 2) gemm_mma(
    const __half* __restrict__ Ah, const __half* __restrict__ Wh,
    const float* __restrict__ bias, float* __restrict__ C, int N,
    __half* __restrict__ qd, __half* __restrict__ kd, __half* __restrict__ vd)
{
    extern __shared__ char smem[];
    const uint32_t sbase = smem_u32(smem);
    const int tid  = threadIdx.x;
    const int wid  = tid >> 5;
    const int lane = tid & 31;
    const int wm = (wid >> 2) * 64;
    const int wn = (wid & 3) * 32;
    const int m0 = blockIdx.y << 7;
    const int n0 = blockIdx.x << 7;

    const __half* asrc = Ah + (size_t)m0 * KK;
    const __half* bsrc = Wh + n0;

    auto prefetch = [&](int kt, int s) {
        uint32_t stb = sbase + s * STAGE_BYTES;
#pragma unroll
        for (int i = 0; i < 4; i++) {
            int cid = i * 256 + tid;
            int row = cid >> 3, c = cid & 7;
            cp16(stb + taddr(0u, row, c),
                 asrc + (size_t)row * KK + kt * 64 + c * 8);
        }
        uint32_t btb = stb + TILE_BYTES;
#pragma unroll
        for (int i = 0; i < 4; i++) {
            int cid = i * 256 + tid;
            int row = cid >> 4, c = cid & 15;
            cp16(btb + taddr256(0u, row, c),
                 bsrc + (size_t)(kt * 64 + row) * N + c * 8);
        }
    };

    float acc[4][4][4];
#pragma unroll
    for (int i = 0; i < 4; i++)
#pragma unroll
        for (int j = 0; j < 4; j++)
#pragma unroll
            for (int k = 0; k < 4; k++) acc[i][j][k] = 0.f;

    prefetch(0, 0); cp_commit();
    prefetch(1, 1); cp_commit();

    const int KCH = KK / 64;   // 16
    for (int kt = 0; kt < KCH; kt++) {
        const int s = kt & 1;
        if (kt == KCH - 1) cp_wait<0>(); else cp_wait<1>();
        __syncthreads();

        const uint32_t ahb = sbase + s * STAGE_BYTES;
        const uint32_t bhb = ahb + TILE_BYTES;

#pragma unroll
        for (int kh = 0; kh < 4; kh++) {
            const int lrow = lane & 15;
            const int lkc  = kh * 2 + (lane >> 4);

            uint32_t a4[4][4];
#pragma unroll
            for (int mt = 0; mt < 4; mt++)
                ldsm4(a4[mt], taddr(ahb, wm + mt * 16 + lrow, lkc));
#pragma unroll
            for (int nh = 0; nh < 2; nh++) {
                uint32_t rb[4];
                const int ck = (wn >> 3) + nh * 2 + (lane >> 4);
                ldsm4t(rb, taddr256(bhb, kh * 16 + lrow, ck));
                const int nb = nh * 2;
#pragma unroll
                for (int mt = 0; mt < 4; mt++) {
                    mma2(acc[mt][nb],     a4[mt], rb[0], rb[1]);
                    mma2(acc[mt][nb + 1], a4[mt], rb[2], rb[3]);
                }
            }
        }
        __syncthreads();
        if (kt + 2 < KCH) { prefetch(kt + 2, s); cp_commit(); }
    }

    if (MODE == 0) {
#pragma unroll
        for (int mt = 0; mt < 4; mt++) {
#pragma unroll
            for (int nt = 0; nt < 4; nt++) {
                int row = m0 + wm + mt * 16 + (lane >> 2);
                int col = n0 + wn + nt * 8 + ((lane & 3) << 1);
                float b0 = __ldg(bias + col), b1 = __ldg(bias + col + 1);
                float* d = acc[mt][nt];
                *(float2*)(C + (size_t)row * N + col) =
                    make_float2(d[0] + b0, d[1] + b1);
                *(float2*)(C + (size_t)(row + 8) * N + col) =
                    make_float2(d[2] + b0, d[3] + b1);
            }
        }
    } else {
        const int region = n0 >> 10;       // 0=Q, 1=K, 2=V
        const int ncol0  = n0 & 1023;
        const float qs = (region == 0) ? 0.125f : 1.0f;
        __half* dst = (region == 0) ? qd : (region == 1) ? kd : vd;
#pragma unroll
        for (int mt = 0; mt < 4; mt++) {
#pragma unroll
            for (int nt = 0; nt < 4; nt++) {
                int row  = m0 + wm + mt * 16 + (lane >> 2);
                int gcol = n0 + wn + nt * 8 + ((lane & 3) << 1);
                int col  = ncol0 + wn + nt * 8 + ((lane & 3) << 1);
                float b0 = __ldg(bias + gcol), b1 = __ldg(bias + gcol + 1);
                float* d = acc[mt][nt];
                *(uint32_t*)(dst + (size_t)row * DD + col) =
                    pkh((d[0] + b0) * qs, (d[1] + b1) * qs);
                *(uint32_t*)(dst + (size_t)(row + 8) * DD + col) =
                    pkh((d[2] + b0) * qs, (d[3] + b1) * qs);
            }
        }
    }
}

// ========================== fused prep kernel (all elementwise) ==========================
__global__ void __launch_bounds__(256) prep_all(
    const float* __restrict__ x, const float* __restrict__ w1,
    const float* __restrict__ w2,
    __half* __restrict__ xh, __half* __restrict__ w1h, __half* __restrict__ w2h)
{
    const int bid = blockIdx.x;
    const int tid = threadIdx.x;
    const float* in;
    __half* outp;
    int i;
    if (bid < 4096)      { in = x;  outp = xh;  i = bid * 256 + tid; }
    else if (bid < 7168) { in = w1; outp = w1h; i = (bid - 4096) * 256 + tid; }
    else                 { in = w2; outp = w2h; i = (bid - 7168) * 256 + tid; }
    float4 v = ((const float4*)in)[i];
    ((uint2*)outp)[i] = make_uint2(pkh(v.x, v.y), pkh(v.z, v.w));
}

// ========================== tensor-core flash attention (pure fp16, paired q-tiles) ==========================
#define FL_SMEM 49152
// layout: Q 0 (16K), then 2 stages of 16K: {K 8K, V 8K}

__global__ void __launch_bounds__(256, 2) flash_attn_tc(
    const __half* __restrict__ qhg, const __half* __restrict__ khg,
    const __half* __restrict__ vhg, __half* __restrict__ outh)
{
    extern __shared__ char sm[];
    const uint32_t sQ  = smem_u32(sm);
    const uint32_t sKV = sQ + 16384;

    const int tid  = threadIdx.x;
    const int wid  = tid >> 5;
    const int lane = tid & 31;
    const int lrow = lane & 15;
    const int wm   = wid << 4;
    const int h    = blockIdx.y;
    const int b    = blockIdx.z;

    // Complementary pairing: qt and 15-qt -> exactly 34 k-tiles per CTA.
    // Process the heavy member first.
    const int qtH = 15 - (int)blockIdx.x;    // blockIdx.x in 0..7 -> qtH 15..8
    const int qtL = (int)blockIdx.x;

#pragma unroll 1
    for (int pass = 0; pass < 2; pass++) {
        const int qt = (pass == 0) ? qtH : qtL;
        const int q0 = qt << 7;
        const int kmax = q0 + wm + 15;   // max k-col this warp needs (causal)

        // ---- Q + first K/V prefetch (one commit group) ----
        {
            const __half* qsrc = qhg + (size_t)(b * SS + q0) * DD + h * HDD;
#pragma unroll
            for (int i = 0; i < 4; i++) {
                int cid = i * 256 + tid;
                int row = cid >> 3, c = cid & 7;
                cp16(sQ + taddr(0u, row, c), qsrc + (size_t)row * DD + c * 8);
            }
        }

        auto pf = [&](int kt, int st) {
            uint32_t sb = sKV + st * 16384;
            const size_t goff = (size_t)(b * SS + (kt << 6)) * DD + h * HDD;
#pragma unroll
            for (int t = 0; t < 4; t++) {
                const __half* gp = (t < 2) ? khg : vhg;
                int cid = ((t & 1) << 8) + tid;
                int row = cid >> 3, c = cid & 7;
                cp16(sb + (uint32_t)((t >> 1) << 13) + taddr(0u, row, c),
                     gp + goff + (size_t)row * DD + c * 8);
            }
        };

        pf(0, 0); cp_commit();

        float o[8][4];
#pragma unroll
        for (int nt = 0; nt < 8; nt++)
#pragma unroll
            for (int k = 0; k < 4; k++) o[nt][k] = 0.f;
        float m0r = -INFINITY, m1r = -INFINITY, l0r = 0.f, l1r = 0.f;

        const int grow0 = q0 + wm + (lane >> 2);
        const int grow1 = grow0 + 8;
        const int nkt = 2 * qt + 2;

        for (int kt = 0; kt < nkt; kt++) {
            const int k0 = kt << 6;
            const int st = kt & 1;
            if (kt + 1 < nkt) {
                pf(kt + 1, st ^ 1); cp_commit();
                cp_wait<1>();
            } else {
                cp_wait<0>();
            }
            __syncthreads();

            const uint32_t sKb = sKV + st * 16384;
            const uint32_t sVb = sKb + 8192;

            // ---- S = Q K^T (warp-uniform skip of fully-masked halves) ----
            float s[8][4];
#pragma unroll
            for (int nt = 0; nt < 8; nt++)
#pragma unroll
                for (int k = 0; k < 4; k++) s[nt][k] = 0.f;

#pragma unroll
            for (int ks = 0; ks < 4; ks++) {
                const int ck = ks * 2 + (lane >> 4);
                uint32_t q4[4];
                ldsm4(q4, taddr(sQ, wm + lrow, ck));
#pragma unroll
                for (int half = 0; half < 2; half++) {
                    if (k0 + half * 32 > kmax) continue;   // S stays exactly 0
                    uint32_t r0[4], r1[4];
                    ldsm4(r0, taddr(sKb, half * 32 + lrow, ck));
                    ldsm4(r1, taddr(sKb, half * 32 + 16 + lrow, ck));
                    const int n0 = half * 4;
                    mma2(s[n0],     q4, r0[0], r0[2]);
                    mma2(s[n0 + 1], q4, r0[1], r0[3]);
                    mma2(s[n0 + 2], q4, r1[0], r1[2]);
                    mma2(s[n0 + 3], q4, r1[1], r1[3]);
                }
            }

            // ---- causal mask ----
            if (k0 + 63 > grow0) {
#pragma unroll
                for (int nt = 0; nt < 8; nt++) {
                    int col = k0 + nt * 8 + ((lane & 3) << 1);
                    if (col > grow0)     s[nt][0] = -1e30f;
                    if (col + 1 > grow0) s[nt][1] = -1e30f;
                    if (col > grow1)     s[nt][2] = -1e30f;
                    if (col + 1 > grow1) s[nt][3] = -1e30f;
                }
            }

            // ---- online softmax ----
            float ml0 = -INFINITY, ml1 = -INFINITY;
#pragma unroll
            for (int nt = 0; nt < 8; nt++) {
                ml0 = fmaxf(ml0, fmaxf(s[nt][0], s[nt][1]));
                ml1 = fmaxf(ml1, fmaxf(s[nt][2], s[nt][3]));
            }
            ml0 = fmaxf(ml0, __shfl_xor_sync(0xffffffffu, ml0, 1));
            ml0 = fmaxf(ml0, __shfl_xor_sync(0xffffffffu, ml0, 2));
            ml1 = fmaxf(ml1, __shfl_xor_sync(0xffffffffu, ml1, 1));
            ml1 = fmaxf(ml1, __shfl_xor_sync(0xffffffffu, ml1, 2));
            float mn0 = fmaxf(m0r, ml0), mn1 = fmaxf(m1r, ml1);
            float c0 = __expf(m0r - mn0), c1 = __expf(m1r - mn1);
            m0r = mn0; m1r = mn1;
            float rs0 = 0.f, rs1 = 0.f;
#pragma unroll
            for (int nt = 0; nt < 8; nt++) {
                s[nt][0] = __expf(s[nt][0] - mn0);
                s[nt][1] = __expf(s[nt][1] - mn0);
                s[nt][2] = __expf(s[nt][2] - mn1);
                s[nt][3] = __expf(s[nt][3] - mn1);
                rs0 += s[nt][0] + s[nt][1];
                rs1 += s[nt][2] + s[nt][3];
            }
            rs0 += __shfl_xor_sync(0xffffffffu, rs0, 1);
            rs0 += __shfl_xor_sync(0xffffffffu, rs0, 2);
            rs1 += __shfl_xor_sync(0xffffffffu, rs1, 1);
            rs1 += __shfl_xor_sync(0xffffffffu, rs1, 2);
            l0r = l0r * c0 + rs0;
            l1r = l1r * c1 + rs1;
            // skip exact-noop rescale (c == 1.0 when max unchanged)
            if (!__all_sync(0xffffffffu, (c0 == 1.f) && (c1 == 1.f))) {
#pragma unroll
                for (int nt = 0; nt < 8; nt++) {
                    o[nt][0] *= c0; o[nt][1] *= c0;
                    o[nt][2] *= c1; o[nt][3] *= c1;
                }
            }

            // ---- O += P V (skip j-slices whose P block is exactly zero) ----
#pragma unroll
            for (int j = 0; j < 4; j++) {
                if (k0 + j * 16 > kmax) continue;   // P fragment all exact zeros
                uint32_t aP[4];
                aP[0] = pkh(s[2 * j][0],     s[2 * j][1]);
                aP[1] = pkh(s[2 * j][2],     s[2 * j][3]);
                aP[2] = pkh(s[2 * j + 1][0], s[2 * j + 1][1]);
                aP[3] = pkh(s[2 * j + 1][2], s[2 * j + 1][3]);
#pragma unroll
                for (int half = 0; half < 2; half++) {
                    const int ck0 = half * 4 + (lane >> 4);
                    const int ck1 = ck0 + 2;
                    uint32_t v0[4], v1[4];
                    ldsm4t(v0, taddr(sVb, j * 16 + lrow, ck0));
                    ldsm4t(v1, taddr(sVb, j * 16 + lrow, ck1));
                    const int c0i = half * 4;
                    mma2(o[c0i],     aP, v0[0], v0[1]);
                    mma2(o[c0i + 1], aP, v0[2], v0[3]);
                    mma2(o[c0i + 2], aP, v1[0], v1[1]);
                    mma2(o[c0i + 3], aP, v1[2], v1[3]);
                }
            }
            __syncthreads();
        }

        // ---- epilogue: normalize, store fp16 merged-head [B*S, D] ----
        float inv0 = 1.f / l0r, inv1 = 1.f / l1r;
        size_t r0 = (size_t)(b * SS + grow0) * DD;
        size_t r1 = (size_t)(b * SS + grow1) * DD;
        int colb = h * HDD + ((lane & 3) << 1);
#pragma unroll
        for (int nt = 0; nt < 8; nt++) {
            int col = colb + nt * 8;
            *(uint32_t*)(outh + r0 + col) = pkh(o[nt][0] * inv0, o[nt][1] * inv0);
            *(uint32_t*)(outh + r1 + col) = pkh(o[nt][2] * inv1, o[nt][3] * inv1);
        }
        // All threads passed the final tile barrier before the epilogue (no smem
        // reads after it), so the next pass's Q cp.async writes are safe.
    }
}

// ---------------------------------------------------------------------------
extern "C" void kernel_launch(void* const* d_in, const int* in_sizes, int n_in,
                              void* d_out, int out_size)
{
    const float* x  = (const float*)d_in[0];
    const float* w1 = (const float*)d_in[1];
    const float* b1 = (const float*)d_in[2];
    const float* w2 = (const float*)d_in[3];
    const float* b2 = (const float*)d_in[4];
    float* out = (float*)d_out;

    __half *xh, *w1h, *w2h, *qh, *kh, *vh, *ah;
    cudaGetSymbolAddress((void**)&xh,  g_xh);
    cudaGetSymbolAddress((void**)&w1h, g_w1h);
    cudaGetSymbolAddress((void**)&w2h, g_w2h);
    cudaGetSymbolAddress((void**)&qh,  g_qh);
    cudaGetSymbolAddress((void**)&kh,  g_kh);
    cudaGetSymbolAddress((void**)&vh,  g_vh);
    cudaGetSymbolAddress((void**)&ah,  g_ah);

    static int inited = 0;
    if (!inited) {
        cudaFuncSetAttribute(gemm_mma<0>,
            cudaFuncAttributeMaxDynamicSharedMemorySize, GEMM_SMEM);
        cudaFuncSetAttribute(gemm_mma<1>,
            cudaFuncAttributeMaxDynamicSharedMemorySize, GEMM_SMEM);
        cudaFuncSetAttribute(flash_attn_tc,
            cudaFuncAttributeMaxDynamicSharedMemorySize, FL_SMEM);
        inited = 1;
    }

    // 0) fused operand prep (pure elementwise converts; weights stay [K,N])
    prep_all<<<8192, 256>>>(x, w1, w2, xh, w1h, w2h);

    // 1) QKV projection with fused Q-scale + fp16 epilogue
    gemm_mma<1><<<dim3(3 * DD / 128, MM / 128), 256, GEMM_SMEM>>>(
        xh, w1h, b1, nullptr, 3 * DD, qh, kh, vh);

    // 2) causal flash attention: paired q-tiles, constant 34 k-tiles per CTA
    flash_attn_tc<<<dim3(SS / 256, HH, BB), 256, FL_SMEM>>>(qh, kh, vh, ah);

    // 3) output projection (fp32 out + bias)
    gemm_mma<0><<<dim3(DD / 128, MM / 128), 256, GEMM_SMEM>>>(
        ah, w2h, b2, out, DD, nullptr, nullptr, nullptr);
}